// round 17
// baseline (speedup 1.0000x reference)
#include <cuda_runtime.h>
#include <cuda_bf16.h>
#include <cstdint>
#include <math.h>

#define BSZ    4
#define LSEQ   2048
#define DMODEL 1024
#define DINNER 2048
#define DSTATE 16
#define DTRANK 64
#define NTOK   (BSZ*LSEQ)        // 8192
#define TT     8
#define HH     16
#define WW     16
#define NFR    (BSZ*TT)          // 32
#define XDBLW  96
#define NOUT   (BSZ*LSEQ*DMODEL) // 8388608

// ---------------- scratch (static device globals; no allocation) -------------
__device__ float g_xcl [BSZ*DINNER*LSEQ];   // x (B, D, L) channel-major
__device__ float g_zt  [BSZ*DINNER*LSEQ];   // z (B, D, L) channel-major
__device__ float g_xct [BSZ*DINNER*LSEQ];   // conv(x) silu (B, D, L) channel-major
__device__ float g_delta[BSZ*DINNER*LSEQ];  // (B, D, L) channel-major
__device__ float g_y   [BSZ*DINNER*LSEQ];   // (B, D, L) channel-major
__device__ float g_xdbl[NTOK*XDBLW];        // (B*L, 96)
__device__ float g_feat[NFR*DINNER];
__device__ float g_f   [DINNER];
__device__ float g_att [DINNER];
__device__ float g_attmax;
__device__ float g_Amax[DSTATE];
__device__ float g_Amin[DSTATE];
__device__ float g_A   [DINNER*DSTATE];

// bf16 split operands: A-side [hi,hi,lo], B-side [hi,lo,hi]
__device__ __nv_bfloat16 g_a_hs [(size_t)NTOK*3*DMODEL];   // 8192 x 3072
__device__ __nv_bfloat16 g_a_x  [(size_t)NTOK*3*DINNER];   // 8192 x 6144
__device__ __nv_bfloat16 g_a_dt [(size_t)NTOK*3*DTRANK];   // 8192 x 192
__device__ __nv_bfloat16 g_a_y  [(size_t)NTOK*3*DINNER];   // 8192 x 6144
__device__ __nv_bfloat16 g_w_in [(size_t)(2*DINNER)*3*DMODEL]; // 4096 x 3072
__device__ __nv_bfloat16 g_w_x  [(size_t)128*3*DINNER];        // 128 x 6144 (96 padded)
__device__ __nv_bfloat16 g_w_dt [(size_t)DINNER*3*DTRANK];     // 2048 x 192
__device__ __nv_bfloat16 g_w_out[(size_t)DMODEL*3*DINNER];     // 1024 x 6144

// exact twiddles: cos/sin(2*pi*k/16)
__constant__ float c_ct[16] = {
    1.0f, 0.92387953251128674f, 0.70710678118654752f, 0.38268343236508978f,
    0.0f, -0.38268343236508978f, -0.70710678118654752f, -0.92387953251128674f,
    -1.0f, -0.92387953251128674f, -0.70710678118654752f, -0.38268343236508978f,
    0.0f, 0.38268343236508978f, 0.70710678118654752f, 0.92387953251128674f};
__constant__ float c_st[16] = {
    0.0f, 0.38268343236508978f, 0.70710678118654752f, 0.92387953251128674f,
    1.0f, 0.92387953251128674f, 0.70710678118654752f, 0.38268343236508978f,
    0.0f, -0.38268343236508978f, -0.70710678118654752f, -0.92387953251128674f,
    -1.0f, -0.92387953251128674f, -0.70710678118654752f, -0.38268343236508978f};

// ================== split conversion: fp32 -> bf16 triple ====================
// PAT 0 (A-side): [hi, hi, lo]   PAT 1 (B-side): [hi, lo, hi]
template<int PAT>
__global__ __launch_bounds__(256)
void split_rows(const float* __restrict__ src, int lda, int rows, int K,
                __nv_bfloat16* __restrict__ dst, int rows_pad)
{
    int idx = blockIdx.x * 256 + threadIdx.x;
    if (idx >= rows_pad * K) return;
    int r = idx / K, k = idx - r * K;
    float v = (r < rows) ? src[(size_t)r * lda + k] : 0.f;
    __nv_bfloat16 hi = __float2bfloat16(v);
    __nv_bfloat16 lo = __float2bfloat16(v - __bfloat162float(hi));
    __nv_bfloat16* o = dst + (size_t)r * 3 * K;
    if (PAT == 0) { o[k] = hi; o[K + k] = hi; o[2 * K + k] = lo; }
    else          { o[k] = hi; o[K + k] = lo; o[2 * K + k] = hi; }
}

// transpose-split: channel-major [b][d][l] fp32 -> A' [(b*L+l)][3*DINNER] [hi,hi,lo]
__global__ __launch_bounds__(256)
void split_trans(const float* __restrict__ src, __nv_bfloat16* __restrict__ dst)
{
    __shared__ float tile[32][33];
    int b = blockIdx.z, d0 = blockIdx.y * 32, l0 = blockIdx.x * 32;
    int tx = threadIdx.x, ty = threadIdx.y;
    for (int i = ty; i < 32; i += 8)
        tile[i][tx] = src[((size_t)b * DINNER + d0 + i) * LSEQ + l0 + tx];
    __syncthreads();
    for (int i = ty; i < 32; i += 8) {
        int l = l0 + i, d = d0 + tx;
        float v = tile[tx][i];
        __nv_bfloat16 hi = __float2bfloat16(v);
        __nv_bfloat16 lo = __float2bfloat16(v - __bfloat162float(hi));
        __nv_bfloat16* o = dst + ((size_t)b * LSEQ + l) * (3 * DINNER);
        o[d] = hi; o[DINNER + d] = hi; o[2 * DINNER + d] = lo;
    }
}

// ==================== warp-mma GEMM: C[m,n] = sum A'[m,k]B'[n,k] =============
// CTA tile 128x128, BK=32 bf16, 256 threads (8 warps, 2x4), warp tile 64x32.
// ldmatrix.x4 fragment loads, 3-stage cp.async pipeline.
// MODE 0: C[m*ldc+n] = v (n < Nreal)
// MODE 1: in_proj split -> g_xcl / aux(z), channel-major
// MODE 2: delta = softplus(v + bias[n]) -> C, channel-major
#define BM  128
#define BN  128
#define BKC 32
#define AST 20                 // u32 stride per smem row (conflict-free)
#define STG 3
#define TW  (128*AST)          // words per tile (A or B)
#define STW (2*TW)             // words per stage
#define GEMM_SMEM (STG*STW*4)  // 61440 bytes

__device__ __forceinline__ uint32_t smem_to_u32(const void* p) {
    uint32_t a;
    asm("{ .reg .u64 t; cvta.to.shared.u64 t, %1; cvt.u32.u64 %0, t; }"
        : "=r"(a) : "l"(p));
    return a;
}
#define CP_ASYNC16(dst, src) \
    asm volatile("cp.async.cg.shared.global [%0], [%1], 16;" \
                 :: "r"(dst), "l"(src) : "memory")
#define CP_COMMIT() asm volatile("cp.async.commit_group;" ::: "memory")
#define CP_WAIT_N(n) asm volatile("cp.async.wait_group %0;" :: "n"(n) : "memory")

__device__ __forceinline__ void ldsm_x4(uint32_t& r0, uint32_t& r1,
                                        uint32_t& r2, uint32_t& r3, uint32_t addr) {
    asm volatile("ldmatrix.sync.aligned.m8n8.x4.shared.b16 {%0,%1,%2,%3}, [%4];"
                 : "=r"(r0), "=r"(r1), "=r"(r2), "=r"(r3) : "r"(addr));
}
__device__ __forceinline__ void mma16816(float* c, const uint32_t* a, const uint32_t* b) {
    asm volatile(
        "mma.sync.aligned.m16n8k16.row.col.f32.bf16.bf16.f32 "
        "{%0,%1,%2,%3}, {%4,%5,%6,%7}, {%8,%9}, {%0,%1,%2,%3};"
        : "+f"(c[0]), "+f"(c[1]), "+f"(c[2]), "+f"(c[3])
        : "r"(a[0]), "r"(a[1]), "r"(a[2]), "r"(a[3]), "r"(b[0]), "r"(b[1]));
}

__device__ __forceinline__ void gemm_issue(
    uint32_t sm_u, const __nv_bfloat16* __restrict__ Abf, int ldaP,
    const __nv_bfloat16* __restrict__ Bbf, int ldbP,
    int m0, int n0, int lrow, int lc, int s)
{
    int buf = s % STG;
    int kb = s << 5;
    uint32_t abase = sm_u + (uint32_t)(buf * STW + lrow * AST) * 4u + (uint32_t)lc * 16u;
    const __nv_bfloat16* ag = Abf + (size_t)(m0 + lrow) * ldaP + kb + lc * 8;
    CP_ASYNC16(abase,      ag);
    CP_ASYNC16(abase + 16, ag + 8);
    uint32_t bbase = sm_u + (uint32_t)(buf * STW + TW + lrow * AST) * 4u + (uint32_t)lc * 16u;
    const __nv_bfloat16* bg = Bbf + (size_t)(n0 + lrow) * ldbP + kb + lc * 8;
    CP_ASYNC16(bbase,      bg);
    CP_ASYNC16(bbase + 16, bg + 8);
}

template<int MODE>
__global__ __launch_bounds__(256, 2)
void mma_nt(const __nv_bfloat16* __restrict__ Abf, int ldaP,
            const __nv_bfloat16* __restrict__ Bbf, int ldbP,
            float* __restrict__ C, int ldc, int Nreal, int KP,
            const float* __restrict__ bias, float* __restrict__ aux)
{
    extern __shared__ __align__(16) uint32_t sm[];
    const uint32_t sm_u = smem_to_u32(sm);
    const int t = threadIdx.x, lane = t & 31, w = t >> 5;
    const int wm = (w >> 2) * 64, wn = (w & 3) * 32;   // 2x4 warp grid
    const int m0 = blockIdx.y * BM, n0 = blockIdx.x * BN;
    const int lrow = t >> 1, lc = (t & 1) * 2;          // loader: row, chunk pair
    const int g = lane >> 3, rw = lane & 7;             // ldmatrix lane mapping

    float acc[4][4][4];
#pragma unroll
    for (int i = 0; i < 4; i++)
#pragma unroll
        for (int j = 0; j < 4; j++)
#pragma unroll
            for (int k = 0; k < 4; k++) acc[i][j][k] = 0.f;

    const int niter = KP >> 5;

    if (0 < niter) gemm_issue(sm_u, Abf, ldaP, Bbf, ldbP, m0, n0, lrow, lc, 0);
    CP_COMMIT();
    if (1 < niter) gemm_issue(sm_u, Abf, ldaP, Bbf, ldbP, m0, n0, lrow, lc, 1);
    CP_COMMIT();

    for (int it = 0; it < niter; it++) {
        CP_WAIT_N(1);
        __syncthreads();
        if (it + 2 < niter)
            gemm_issue(sm_u, Abf, ldaP, Bbf, ldbP, m0, n0, lrow, lc, it + 2);
        CP_COMMIT();

        const int buf = it % STG;
        const uint32_t sa = sm_u + (uint32_t)(buf * STW) * 4u;
        const uint32_t sb = sa + (uint32_t)TW * 4u;
#pragma unroll
        for (int ks = 0; ks < 2; ks++) {
            uint32_t af[4][4];
#pragma unroll
            for (int mt = 0; mt < 4; mt++) {
                int row = wm + mt * 16 + ((g & 1) << 3) + rw;
                uint32_t addr = sa + (uint32_t)(row * AST + ((ks << 1) + (g >> 1)) * 4) * 4u;
                ldsm_x4(af[mt][0], af[mt][1], af[mt][2], af[mt][3], addr);
            }
            uint32_t bf[4][2];
#pragma unroll
            for (int ntp = 0; ntp < 2; ntp++) {
                int row = wn + ntp * 16 + ((g >> 1) << 3) + rw;
                uint32_t addr = sb + (uint32_t)(row * AST + ((ks << 1) + (g & 1)) * 4) * 4u;
                ldsm_x4(bf[2 * ntp][0], bf[2 * ntp][1],
                        bf[2 * ntp + 1][0], bf[2 * ntp + 1][1], addr);
            }
#pragma unroll
            for (int mt = 0; mt < 4; mt++)
#pragma unroll
                for (int nt = 0; nt < 4; nt++)
                    mma16816(acc[mt][nt], af[mt], bf[nt]);
        }
    }

    // epilogue
#pragma unroll
    for (int mt = 0; mt < 4; mt++) {
#pragma unroll
        for (int nt = 0; nt < 4; nt++) {
            int mb = m0 + wm + mt * 16 + (lane >> 2);
            int nb = n0 + wn + nt * 8 + (lane & 3) * 2;
#pragma unroll
            for (int e = 0; e < 4; e++) {
                int m = mb + (e >> 1) * 8;
                int n = nb + (e & 1);
                float v = acc[mt][nt][e];
                if (MODE == 0) {
                    if (n < Nreal) C[(size_t)m * ldc + n] = v;
                } else if (MODE == 1) {
                    int b = m >> 11, l = m & 2047;
                    if (n < DINNER)
                        g_xcl[((size_t)b * DINNER + n) * LSEQ + l] = v;
                    else
                        aux[((size_t)b * DINNER + (n - DINNER)) * LSEQ + l] = v;
                } else {
                    int b = m >> 11, l = m & 2047;
                    float x = v + bias[n];
                    float sp = (x > 20.f) ? x : log1pf(__expf(x));
                    C[((size_t)b * DINNER + n) * LSEQ + l] = sp;
                }
            }
        }
    }
}

// ---------------- FFT bands / features (X staged in smem, no spills) ----------
#define BANDS_SMEM (256*128*4)
__global__ __launch_bounds__(128)
void bands_kernel()
{
    extern __shared__ float Xs[];   // [256][128] transposed: Xs[i*128 + tid]
    int t = threadIdx.x;
    int gid = blockIdx.x * 128 + t;   // 65536 total
    int c  = gid & 2047;
    int fr = gid >> 11;
    int b  = fr >> 3, tt = fr & 7;

    const float* px = g_xcl + ((size_t)b * DINNER + c) * LSEQ + tt * (HH * WW);
#pragma unroll 4
    for (int i = 0; i < HH * WW; i++) Xs[i * 128 + t] = px[i];

    double bands[8];
#pragma unroll
    for (int k = 0; k < 8; k++) bands[k] = 0.0;

#pragma unroll 1
    for (int v = 0; v < 9; v++) {
        float Rre[16], Rim[16];
#pragma unroll
        for (int h = 0; h < 16; h++) {
            float re = 0.f, im = 0.f;
#pragma unroll
            for (int w = 0; w < 16; w++) {
                int ph = (v * w) & 15;
                float xv = Xs[(h * 16 + w) * 128 + t];
                re += xv * c_ct[ph];
                im -= xv * c_st[ph];
            }
            Rre[h] = re; Rim[h] = im;
        }
        int jj = (v + 4) % 9;                 // fftshift width (n=9)
        float dw = (float)(jj - 4) / 9.0f;
        float dw2 = dw * dw;
#pragma unroll 1
        for (int u = 0; u < 16; u++) {
            float Fre = 0.f, Fim = 0.f;
#pragma unroll
            for (int h = 0; h < 16; h++) {
                int ph = (u * h) & 15;
                float cr = c_ct[ph], sr = c_st[ph];
                Fre += Rre[h] * cr + Rim[h] * sr;
                Fim += Rim[h] * cr - Rre[h] * sr;
            }
            float mag = sqrtf(Fre * Fre + Fim * Fim + 1e-8f);
            int i2 = (u + 8) & 15;            // fftshift height (n=16)
            float dh = (float)(i2 - 8) / 16.0f;
            float rr = sqrtf(dh * dh + dw2);
            int band = (int)(rr * 8.0f);
            if (band > 7) band = 7;
            bands[band] += (double)mag;
        }
    }
    double tot = 0.0;
#pragma unroll
    for (int k = 0; k < 8; k++) tot += bands[k];
    double inv = 1.0 / (tot + 1e-8);
    g_feat[(size_t)fr * DINNER + c] =
        (float)((bands[4] + bands[5] + bands[6] + bands[7]) * inv);
}

// ---------------- loss ----------------------------------------------------------
__global__ __launch_bounds__(256)
void loss_kernel(float* __restrict__ out, int out_size)
{
    __shared__ double red[256];
    __shared__ double invn[NFR];
    int tid = threadIdx.x;
    for (int fr = 0; fr < NFR; fr++) {
        double s = 0.0;
        for (int c = tid; c < DINNER; c += 256) {
            double v = (double)g_feat[fr * DINNER + c];
            s += v * v;
        }
        red[tid] = s; __syncthreads();
        for (int o = 128; o > 0; o >>= 1) {
            if (tid < o) red[tid] += red[tid + o];
            __syncthreads();
        }
        if (tid == 0) invn[fr] = 1.0 / fmax(sqrt(red[0]), 1e-12);
        __syncthreads();
    }
    double s = 0.0;
    for (int c = tid; c < DINNER; c += 256) {
        double gsum = 0.0;
        for (int fr = 0; fr < NFR; fr++) gsum += (double)g_feat[fr * DINNER + c] * invn[fr];
        s += gsum * gsum;
    }
    red[tid] = s; __syncthreads();
    for (int o = 128; o > 0; o >>= 1) {
        if (tid < o) red[tid] += red[tid + o];
        __syncthreads();
    }
    if (tid == 0) {
        float loss = (float)(1.0 - red[0] / (double)(NFR * NFR));
        for (int i = NOUT; i < out_size; i++) out[i] = loss;
    }
}

// ---------------- f = softmax(mean features) -----------------------------------
__global__ __launch_bounds__(256)
void fsoftmax_kernel()
{
    __shared__ float red[256];
    int tid = threadIdx.x;
    float lmax = -1e30f;
    for (int c = tid; c < DINNER; c += 256) {
        float s = 0.f;
        for (int fr = 0; fr < NFR; fr++) s += g_feat[fr * DINNER + c];
        float mu = s / (float)NFR;
        g_f[c] = mu;
        lmax = fmaxf(lmax, mu);
    }
    red[tid] = lmax; __syncthreads();
    for (int o = 128; o > 0; o >>= 1) {
        if (tid < o) red[tid] = fmaxf(red[tid], red[tid + o]);
        __syncthreads();
    }
    float mx = red[0]; __syncthreads();
    float lsum = 0.f;
    for (int c = tid; c < DINNER; c += 256) lsum += expf(g_f[c] - mx);
    red[tid] = lsum; __syncthreads();
    for (int o = 128; o > 0; o >>= 1) {
        if (tid < o) red[tid] += red[tid + o];
        __syncthreads();
    }
    float tot = red[0]; __syncthreads();
    for (int c = tid; c < DINNER; c += 256) g_f[c] = expf(g_f[c] - mx) / tot;
}

// ---------------- A stats -------------------------------------------------------
__global__ __launch_bounds__(256)
void astats_kernel(const float* __restrict__ A_log)
{
    __shared__ float red[256];
    int tid = threadIdx.x;
    float lmax = 0.f;
    for (int d = tid; d < DINNER; d += 256) {
        float s = 0.f;
        for (int n = 0; n < DSTATE; n++) {
            float e = expf(A_log[d * DSTATE + n]);
            s += e * e;
        }
        float a = sqrtf(s);
        g_att[d] = a;
        lmax = fmaxf(lmax, a);
    }
    red[tid] = lmax; __syncthreads();
    for (int o = 128; o > 0; o >>= 1) {
        if (tid < o) red[tid] = fmaxf(red[tid], red[tid + o]);
        __syncthreads();
    }
    if (tid == 0) g_attmax = red[0];
    if (tid < DSTATE) {
        float mx = -1e30f, mn = 1e30f;
        for (int d = 0; d < DINNER; d++) {
            float v = A_log[d * DSTATE + tid];
            mx = fmaxf(mx, v); mn = fminf(mn, v);
        }
        g_Amax[tid] = mx; g_Amin[tid] = mn;
    }
}

// ---------------- A = -exp(blend(A_log)) ---------------------------------------
__global__ __launch_bounds__(256)
void acompute_kernel(const float* __restrict__ A_log)
{
    int idx = blockIdx.x * blockDim.x + threadIdx.x;
    if (idx >= DINNER * DSTATE) return;
    int d = idx >> 4, n = idx & 15;
    float attn = g_att[d] / (g_attmax + 1e-8f);
    float alpha = fminf(fmaxf(g_f[d] * (1.f - attn), 0.f), 1.f);
    float al = A_log[idx];
    float anew = (1.f - alpha) * al + alpha * (g_Amax[n] + g_Amin[n] - al);
    g_A[idx] = -expf(anew);
}

// ---------------- depthwise causal conv + silu (channel-major in & out) --------
__global__ __launch_bounds__(256)
void conv_kernel(const float* __restrict__ w, const float* __restrict__ bias)
{
    int l = blockIdx.x * 256 + threadIdx.x;
    int d = blockIdx.y, b = blockIdx.z;
    const float* row = g_xcl + ((size_t)b * DINNER + d) * LSEQ;
    float w0 = w[d * 4 + 0], w1 = w[d * 4 + 1], w2 = w[d * 4 + 2], w3 = w[d * 4 + 3];
    float x0 = (l >= 3) ? row[l - 3] : 0.f;
    float x1 = (l >= 2) ? row[l - 2] : 0.f;
    float x2 = (l >= 1) ? row[l - 1] : 0.f;
    float x3 = row[l];
    float v = x0 * w0 + x1 * w1 + x2 * w2 + x3 * w3 + bias[d];
    g_xct[((size_t)b * DINNER + d) * LSEQ + l] = v / (1.f + __expf(-v));
}

// ---------------- selective scan: thread per (b, d, n) -------------------------
__global__ __launch_bounds__(256)
void scan_kernel(const float* __restrict__ Dp)
{
    int gid = blockIdx.x * blockDim.x + threadIdx.x;  // 131072
    int grp = gid >> 4;
    int n = gid & 15;
    int b = grp >> 11;
    int d = grp & 2047;

    float a  = g_A[d * DSTATE + n];
    float Dd = Dp[d];
    size_t base = ((size_t)b * DINNER + d) * LSEQ;
    const float* dptr  = g_delta + base;
    const float* uptr  = g_xct   + base;
    const float* zptr  = g_zt    + base;
    const float* bcptr = g_xdbl  + (size_t)b * LSEQ * XDBLW;
    float*       yptr  = g_y     + base;

    float s = 0.f;
    for (int l = 0; l < LSEQ; l++) {
        float dt = dptr[l];
        float u  = uptr[l];
        float Bn = bcptr[l * XDBLW + DTRANK + n];
        float Cn = bcptr[l * XDBLW + DTRANK + DSTATE + n];
        s = s * __expf(dt * a) + dt * u * Bn;
        float p = s * Cn;
        p += __shfl_xor_sync(0xffffffffu, p, 1);
        p += __shfl_xor_sync(0xffffffffu, p, 2);
        p += __shfl_xor_sync(0xffffffffu, p, 4);
        p += __shfl_xor_sync(0xffffffffu, p, 8);
        if (n == 0) {
            float zv = zptr[l];
            float sil = zv / (1.f + __expf(-zv));
            yptr[l] = (p + u * Dd) * sil;
        }
    }
}

// ---------------- launch --------------------------------------------------------
extern "C" void kernel_launch(void* const* d_in, const int* in_sizes, int n_in,
                              void* d_out, int out_size)
{
    int off = (n_in >= 13) ? 4 : 1;
    const float* hs    = (const float*)d_in[0];
    const float* inw   = (const float*)d_in[off + 0];
    const float* convw = (const float*)d_in[off + 1];
    const float* convb = (const float*)d_in[off + 2];
    const float* xpw   = (const float*)d_in[off + 3];
    const float* dtw   = (const float*)d_in[off + 4];
    const float* dtb   = (const float*)d_in[off + 5];
    const float* Alog  = (const float*)d_in[off + 6];
    const float* Dp    = (const float*)d_in[off + 7];
    const float* outw  = (const float*)d_in[off + 8];
    float* out = (float*)d_out;

    float *p_zt, *p_delta, *p_xct, *p_y, *p_xdbl, *p_xcl;
    cudaGetSymbolAddress((void**)&p_xcl,   g_xcl);
    cudaGetSymbolAddress((void**)&p_zt,    g_zt);
    cudaGetSymbolAddress((void**)&p_xct,   g_xct);
    cudaGetSymbolAddress((void**)&p_delta, g_delta);
    cudaGetSymbolAddress((void**)&p_y,     g_y);
    cudaGetSymbolAddress((void**)&p_xdbl,  g_xdbl);
    __nv_bfloat16 *p_a_hs, *p_a_x, *p_a_dt, *p_a_y, *p_w_in, *p_w_x, *p_w_dt, *p_w_out;
    cudaGetSymbolAddress((void**)&p_a_hs,  g_a_hs);
    cudaGetSymbolAddress((void**)&p_a_x,   g_a_x);
    cudaGetSymbolAddress((void**)&p_a_dt,  g_a_dt);
    cudaGetSymbolAddress((void**)&p_a_y,   g_a_y);
    cudaGetSymbolAddress((void**)&p_w_in,  g_w_in);
    cudaGetSymbolAddress((void**)&p_w_x,   g_w_x);
    cudaGetSymbolAddress((void**)&p_w_dt,  g_w_dt);
    cudaGetSymbolAddress((void**)&p_w_out, g_w_out);

    // opt-in dynamic smem limits (idempotent host calls; safe under capture)
    cudaFuncSetAttribute(mma_nt<0>, cudaFuncAttributeMaxDynamicSharedMemorySize, GEMM_SMEM);
    cudaFuncSetAttribute(mma_nt<1>, cudaFuncAttributeMaxDynamicSharedMemorySize, GEMM_SMEM);
    cudaFuncSetAttribute(mma_nt<2>, cudaFuncAttributeMaxDynamicSharedMemorySize, GEMM_SMEM);
    cudaFuncSetAttribute(bands_kernel, cudaFuncAttributeMaxDynamicSharedMemorySize, BANDS_SMEM);

    // ---- conversions: weights (B-side PAT1) and hs (A-side PAT0)
    split_rows<1><<<(4096 * 1024 + 255) / 256, 256>>>(inw, DMODEL, 4096, DMODEL, p_w_in, 4096);
    split_rows<1><<<(128 * 2048 + 255) / 256, 256>>>(xpw, DINNER, XDBLW, DINNER, p_w_x, 128);
    split_rows<1><<<(2048 * 64 + 255) / 256, 256>>>(dtw, DTRANK, DINNER, DTRANK, p_w_dt, DINNER);
    split_rows<1><<<(1024 * 2048 + 255) / 256, 256>>>(outw, DINNER, DMODEL, DINNER, p_w_out, DMODEL);
    split_rows<0><<<(NTOK * DMODEL + 255) / 256, 256>>>(hs, DMODEL, NTOK, DMODEL, p_a_hs, NTOK);

    // 1. in_proj: (8192 x 3072) x (4096 x 3072)^T -> x_cl + z (channel-major)
    mma_nt<1><<<dim3(4096 / BN, NTOK / BM), 256, GEMM_SMEM>>>(
        p_a_hs, 3 * DMODEL, p_w_in, 3 * DMODEL, nullptr, 0, 4096, 3 * DMODEL, nullptr, p_zt);

    // 2. FFT bands -> features; loss / softmax / A stats / A blend
    bands_kernel<<<(NFR * DINNER) / 128, 128, BANDS_SMEM>>>();
    loss_kernel<<<1, 256>>>(out, out_size);
    fsoftmax_kernel<<<1, 256>>>();
    astats_kernel<<<1, 256>>>(Alog);
    acompute_kernel<<<(DINNER * DSTATE + 255) / 256, 256>>>(Alog);

    // 3. depthwise conv + silu (channel-major)
    conv_kernel<<<dim3(LSEQ / 256, DINNER, BSZ), 256>>>(convw, convb);

    // 4. x_proj: xct -> A' (transpose split), then GEMM -> xdbl (token-major, ld 96)
    split_trans<<<dim3(LSEQ / 32, DINNER / 32, BSZ), dim3(32, 8)>>>(p_xct, p_a_x);
    mma_nt<0><<<dim3(1, NTOK / BM), 256, GEMM_SMEM>>>(
        p_a_x, 3 * DINNER, p_w_x, 3 * DINNER, p_xdbl, XDBLW, XDBLW, 3 * DINNER, nullptr, nullptr);

    // 5. dt_proj + softplus -> delta (channel-major)
    split_rows<0><<<(NTOK * DTRANK + 255) / 256, 256>>>(p_xdbl, XDBLW, NTOK, DTRANK, p_a_dt, NTOK);
    mma_nt<2><<<dim3(DINNER / BN, NTOK / BM), 256, GEMM_SMEM>>>(
        p_a_dt, 3 * DTRANK, p_w_dt, 3 * DTRANK, p_delta, 0, DINNER, 3 * DTRANK, dtb, nullptr);

    // 6. selective scan -> y (channel-major)
    scan_kernel<<<(BSZ * DINNER * DSTATE) / 256, 256>>>(Dp);

    // 7. out_proj: y -> A' (transpose split), GEMM -> out
    split_trans<<<dim3(LSEQ / 32, DINNER / 32, BSZ), dim3(32, 8)>>>(p_y, p_a_y);
    mma_nt<0><<<dim3(DMODEL / BN, NTOK / BM), 256, GEMM_SMEM>>>(
        p_a_y, 3 * DINNER, p_w_out, 3 * DINNER, out, DMODEL, DMODEL, 3 * DINNER, nullptr, nullptr);
}